// round 8
// baseline (speedup 1.0000x reference)
#include <cuda_runtime.h>
#include <cuda_bf16.h>

#define PP   4096
#define TT   128
#define AA   32
#define KSEL 409
#define INF_F 1e30f
#define TEMP_F 0.5f
#define FULLM 0xffffffffu

__device__ float    g_dists[PP];
__device__ int      g_eidx[KSEL];
__device__ float    g_ew[KSEL];
__device__ float    g_ssum;

// ---------------------------------------------------------------------------
// Kernel 1: DTW min-plus DP. TWO problems per warp (16-lane segments),
// 8 cols/lane. Row solve: D_j = S_j + prefmin_{k<=j}(e_k - S_k).
// Segment shfls (width=16) cut SHFL count per problem-row ~2.4x; total
// instruction count per problem-row drops ~25% -> issue-bound time halves,
// pushing the kernel toward the 32us DRAM floor for the 256MB stream.
// ---------------------------------------------------------------------------
__device__ __forceinline__ void sum_scan8(float4 a, float4 b, int sl,
                                          float S[8], float& sum_ex) {
    float s0 = a.x, s1 = s0 + a.y, s2 = s1 + a.z, s3 = s2 + a.w;
    float s4 = s3 + b.x, s5 = s4 + b.y, s6 = s5 + b.z, s7 = s6 + b.w;
    float t = s7;
    #pragma unroll
    for (int d = 1; d < 16; d <<= 1) {
        float o = __shfl_up_sync(FULLM, t, d, 16);
        if (sl >= d) t += o;
    }
    sum_ex = t - s7;   // segment-exclusive total (0 at segment lane 0)
    S[0] = sum_ex + s0; S[1] = sum_ex + s1; S[2] = sum_ex + s2; S[3] = sum_ex + s3;
    S[4] = sum_ex + s4; S[5] = sum_ex + s5; S[6] = sum_ex + s6; S[7] = t;
}

__global__ void __launch_bounds__(128) dtw_kernel(const float* __restrict__ obs) {
    int lane = threadIdx.x & 31;
    int warp = (blockIdx.x * blockDim.x + threadIdx.x) >> 5;
    int sl   = lane & 15;          // lane within 16-lane segment
    int half = lane >> 4;          // which problem of the pair
    int p    = warp * 2 + half;

    const float4* base = (const float4*)obs + (size_t)p * (TT * TT / 4) + 2 * sl;

    // prefetch depth 3 rows (2 float4 per row per lane)
    float4 a0 = __ldcs(base),      b0 = __ldcs(base + 1);
    float4 a1 = __ldcs(base + 32), b1 = __ldcs(base + 33);
    float4 a2 = __ldcs(base + 64), b2 = __ldcs(base + 65);

    float S[8], sum_ex;
    sum_scan8(a0, b0, sl, S, sum_ex);

    float pd0 = INF_F, pd1 = INF_F, pd2 = INF_F, pd3 = INF_F;
    float pd4 = INF_F, pd5 = INF_F, pd6 = INF_F, pd7 = INF_F;
    float lp = (sl == 0) ? 0.0f : INF_F;   // Dprev[8*sl-1] boundary for row 0

    for (int i = 0; i < TT; ++i) {
        int nx = (i + 3 < TT) ? (i + 3) : (TT - 1);
        float4 a3 = __ldcs(base + nx * 32);
        float4 b3 = __ldcs(base + nx * 32 + 1);

        float e0 = fminf(pd0, lp)  + a0.x;
        float e1 = fminf(pd1, pd0) + a0.y;
        float e2 = fminf(pd2, pd1) + a0.z;
        float e3 = fminf(pd3, pd2) + a0.w;
        float e4 = fminf(pd4, pd3) + b0.x;
        float e5 = fminf(pd5, pd4) + b0.y;
        float e6 = fminf(pd6, pd5) + b0.z;
        float e7 = fminf(pd7, pd6) + b0.w;

        // local inclusive prefix-min of m_j = e_j - S_j
        float l0 = e0 - S[0];
        float l1 = fminf(l0, e1 - S[1]);
        float l2 = fminf(l1, e2 - S[2]);
        float l3 = fminf(l2, e3 - S[3]);
        float l4 = fminf(l3, e4 - S[4]);
        float l5 = fminf(l4, e5 - S[5]);
        float l6 = fminf(l5, e6 - S[6]);
        float l7 = fminf(l6, e7 - S[7]);

        // segment inclusive min-scan (unpredicated: OOR returns own value)
        float g = l7;
        #pragma unroll
        for (int d = 1; d < 16; d <<= 1)
            g = fminf(g, __shfl_up_sync(FULLM, g, d, 16));

        float ex = __shfl_up_sync(FULLM, g, 1, 16);  // exclusive min carry
        if (sl == 0) ex = INF_F;

        pd0 = S[0] + fminf(ex, l0);
        pd1 = S[1] + fminf(ex, l1);
        pd2 = S[2] + fminf(ex, l2);
        pd3 = S[3] + fminf(ex, l3);
        pd4 = S[4] + fminf(ex, l4);
        pd5 = S[5] + fminf(ex, l5);
        pd6 = S[6] + fminf(ex, l6);
        pd7 = S[7] + fminf(ex, l7);

        // lp for next row: pd7[sl-1] = S7[sl-1] + g[sl-1] = sum_ex + ex
        // (segment lane 0: ex=INF -> lp=INF, correct boundary for rows >= 1)
        lp = sum_ex + ex;

        // next row's sums (independent of DP chain)
        sum_scan8(a1, b1, sl, S, sum_ex);

        a0 = a1; b0 = b1; a1 = a2; b1 = b2; a2 = a3; b2 = b3;
    }
    if (sl == 15) g_dists[p] = pd7;
}

// ---------------------------------------------------------------------------
// Kernel 2: single-block exact radix top-K + weights + elite compaction.
// ---------------------------------------------------------------------------
__global__ void __launch_bounds__(1024) select_kernel() {
    __shared__ unsigned hist[256];
    __shared__ unsigned wsum[32];
    __shared__ float    fred[32];
    __shared__ int      ired[32];
    __shared__ int      pofs[32];
    __shared__ float    s_min, s_Se;
    __shared__ unsigned s_prefix;
    __shared__ int      s_krem, s_cnt_lt;

    int tid = threadIdx.x, lane = tid & 31, wid = tid >> 5;

    float d[4]; unsigned u[4];
    float lmin = INF_F;
    #pragma unroll
    for (int e = 0; e < 4; ++e) {
        float x = g_dists[tid * 4 + e];
        d[e] = x;
        unsigned b = __float_as_uint(x);
        u[e] = b ^ ((b & 0x80000000u) ? 0xFFFFFFFFu : 0x80000000u);
        lmin = fminf(lmin, x);
    }
    if (tid == 0) { s_prefix = 0; s_krem = KSEL; s_cnt_lt = 0; }

    #pragma unroll
    for (int o = 16; o; o >>= 1) lmin = fminf(lmin, __shfl_xor_sync(FULLM, lmin, o));
    if (lane == 0) fred[wid] = lmin;
    __syncthreads();
    if (wid == 0) {
        float v = fred[lane];
        #pragma unroll
        for (int o = 16; o; o >>= 1) v = fminf(v, __shfl_xor_sync(FULLM, v, o));
        if (lane == 0) s_min = v;
    }
    __syncthreads();

    for (int shift = 24; shift >= 0; shift -= 8) {
        if (tid < 256) hist[tid] = 0;
        __syncthreads();
        unsigned pref  = s_prefix;
        int      krem  = s_krem;
        unsigned hmask = (shift == 24) ? 0u : (0xFFFFFFFFu << (shift + 8));
        #pragma unroll
        for (int e = 0; e < 4; ++e)
            if ((u[e] & hmask) == pref) atomicAdd(&hist[(u[e] >> shift) & 255], 1u);
        __syncthreads();
        unsigned v = 0, inc = 0;
        if (tid < 256) {
            v = hist[tid];
            inc = v;
            #pragma unroll
            for (int o = 1; o < 32; o <<= 1) {
                unsigned x = __shfl_up_sync(FULLM, inc, o);
                if (lane >= o) inc += x;
            }
            if (lane == 31) wsum[wid] = inc;
        }
        __syncthreads();
        if (tid < 256) {
            unsigned off = 0;
            #pragma unroll
            for (int k = 0; k < 8; ++k) off += (k < wid) ? wsum[k] : 0u;
            unsigned cum  = off + inc;
            unsigned prev = cum - v;
            if (prev < (unsigned)krem && (unsigned)krem <= cum) {
                s_prefix = pref | ((unsigned)tid << shift);
                s_krem   = krem - (int)prev;
            }
        }
        __syncthreads();
    }
    unsigned tau = s_prefix;

    int clt = 0, tc = 0;
    #pragma unroll
    for (int e = 0; e < 4; ++e) { clt += (u[e] < tau); tc += (u[e] == tau); }
    atomicAdd(&s_cnt_lt, clt);

    int incl = tc;
    #pragma unroll
    for (int o = 1; o < 32; o <<= 1) { int v = __shfl_up_sync(FULLM, incl, o); if (lane >= o) incl += v; }
    if (lane == 31) ired[wid] = incl;
    __syncthreads();
    if (wid == 0) {
        int v = ired[lane], s = v;
        #pragma unroll
        for (int o = 1; o < 32; o <<= 1) { int w2 = __shfl_up_sync(FULLM, s, o); if (lane >= o) s += w2; }
        ired[lane] = s - v;
    }
    __syncthreads();

    int trank = ired[wid] + (incl - tc);
    int need  = KSEL - s_cnt_lt;
    float mind = s_min;

    bool  sel[4]; float ws[4]; float esum = 0.f; int nsel = 0;
    #pragma unroll
    for (int e = 0; e < 4; ++e) {
        bool s = (u[e] < tau);
        if (u[e] == tau) { s = (trank < need); trank++; }
        sel[e] = s;
        float w = s ? expf(TEMP_F * (mind - d[e])) : 0.f;
        ws[e] = w; esum += w; nsel += s;
    }

    float se = esum;
    #pragma unroll
    for (int o = 16; o; o >>= 1) se += __shfl_xor_sync(FULLM, se, o);
    if (lane == 0) fred[wid] = se;
    __syncthreads();
    if (wid == 0) {
        float v = fred[lane];
        #pragma unroll
        for (int o = 16; o; o >>= 1) v += __shfl_xor_sync(FULLM, v, o);
        if (lane == 0) s_Se = v;
    }
    __syncthreads();
    float Se = s_Se;

    int pincl = nsel;
    #pragma unroll
    for (int o = 1; o < 32; o <<= 1) { int v = __shfl_up_sync(FULLM, pincl, o); if (lane >= o) pincl += v; }
    if (lane == 31) pofs[wid] = pincl;
    __syncthreads();
    if (wid == 0) {
        int v = pofs[lane], s = v;
        #pragma unroll
        for (int o = 1; o < 32; o <<= 1) { int w2 = __shfl_up_sync(FULLM, s, o); if (lane >= o) s += w2; }
        pofs[lane] = s - v;
    }
    __syncthreads();
    int pos = pofs[wid] + (pincl - nsel);

    float ssl = 0.f;
    #pragma unroll
    for (int e = 0; e < 4; ++e) {
        if (sel[e]) {
            float sc = ws[e] / Se;
            g_eidx[pos] = tid * 4 + e;
            g_ew[pos]   = sc;
            pos++;
            ssl += sc;
        }
    }

    #pragma unroll
    for (int o = 16; o; o >>= 1) ssl += __shfl_xor_sync(FULLM, ssl, o);
    if (lane == 0) fred[wid] = ssl;
    __syncthreads();
    if (wid == 0) {
        float v = fred[lane];
        #pragma unroll
        for (int o = 16; o; o >>= 1) v += __shfl_xor_sync(FULLM, v, o);
        if (lane == 0) g_ssum = v;
    }
}

// ---------------------------------------------------------------------------
// Kernel 3: weighted mean/std over the compacted elite list. One block per t.
// ---------------------------------------------------------------------------
__global__ void __launch_bounds__(512) reduce_kernel(const float* __restrict__ means,
                                                     const float* __restrict__ stds,
                                                     const float* __restrict__ noise,
                                                     float* __restrict__ out) {
    __shared__ float s1s[16][AA];
    __shared__ float s2s[16][AA];
    int t  = blockIdx.x;
    int a  = threadIdx.x & 31;
    int wg = threadIdx.x >> 5;

    float mn = means[t * AA + a];
    float sd = stds[t * AA + a];
    const float* np = noise + (size_t)t * PP * AA;

    float s1 = 0.f, s2 = 0.f;
    #pragma unroll 4
    for (int k = wg; k < KSEL; k += 16) {
        int   p = g_eidx[k];
        float w = g_ew[k];
        float x = fmaf(sd, __ldg(&np[(size_t)p * AA + a]), mn);
        x = fminf(fmaxf(x, -1.f), 1.f);
        s1 = fmaf(w, x, s1);
        s2 = fmaf(w * x, x, s2);
    }
    s1s[wg][a] = s1; s2s[wg][a] = s2;
    __syncthreads();

    if (wg == 0) {
        float S1 = 0.f, S2 = 0.f;
        #pragma unroll
        for (int k = 0; k < 16; ++k) { S1 += s1s[k][a]; S2 += s2s[k][a]; }
        float ssum  = g_ssum;
        float denom = ssum + 1e-9f;
        float m   = S1 / denom;
        float var = (S2 - 2.f * m * S1 + m * m * ssum) / denom;
        var = fmaxf(var, 0.f);
        float st = sqrtf(var);
        st = fminf(fmaxf(st, 0.05f), 1.0f);
        out[t * AA + a]           = 0.1f * mn + 0.9f * m;
        out[TT * AA + t * AA + a] = st;
    }
}

extern "C" void kernel_launch(void* const* d_in, const int* in_sizes, int n_in,
                              void* d_out, int out_size) {
    const float* obs   = (const float*)d_in[0];  // [P, T, T]
    const float* means = (const float*)d_in[1];  // [T, 1, A]
    const float* stds  = (const float*)d_in[2];  // [T, 1, A]
    const float* noise = (const float*)d_in[3];  // [T, P, A]
    float* out = (float*)d_out;                  // [2, T, 1, A]

    dtw_kernel<<<512, 128>>>(obs);               // 2048 warps, 2 problems each
    select_kernel<<<1, 1024>>>();
    reduce_kernel<<<TT, 512>>>(means, stds, noise, out);
}

// round 11
// speedup vs baseline: 1.3422x; 1.3422x over previous
#include <cuda_runtime.h>
#include <cuda_bf16.h>

#define PP   4096
#define TT   128
#define AA   32
#define KSEL 409
#define INF_F 1e30f
#define TEMP_F 0.5f
#define FULLM 0xffffffffu
#define RING   64      // ring rows (power of 2); retention: reuse dist 52 > read window 31
#define MARGIN 12      // cp.async rows in flight (~700 cyc of slack > 577 DRAM lat)

__device__ float    g_dists[PP];
__device__ int      g_eidx[KSEL];
__device__ float    g_ew[KSEL];
__device__ float    g_ssum;

// ---------------------------------------------------------------------------
// Kernel 1: DTW min-plus DP, skewed anti-diagonal. One 32-thread block per p.
// Lane l owns cols 4l..4l+3; at step s it computes row i = s - l.
// Per step: 1 shfl (neighbor col, 1 full step of slack -> latency hidden),
// 4-cell serial chain (~58 cyc), 1 conflict-free LDS.128 from a cp.async-fed
// 64-row smem ring (each lane reads ONLY its own 16B slice -> no cross-lane
// smem ordering needed). Pre-active lanes (i<0) get c=INF so their d regs
// stay INF until activation. Trailing (i>=TT) garbage is never consumed.
// ---------------------------------------------------------------------------
__global__ void __launch_bounds__(32) dtw_kernel(const float* __restrict__ obs) {
    __shared__ float ring[RING * TT];   // 32 KB
    int lane = threadIdx.x;
    int p = blockIdx.x;

    const float* gp = obs + (size_t)p * (TT * TT) + lane * 4;
    unsigned sbase = (unsigned)__cvta_generic_to_shared(ring) + (lane << 4);

    // prologue: rows 0..MARGIN-1 in flight, one commit group per row
    #pragma unroll
    for (int r = 0; r < MARGIN; ++r) {
        unsigned dst = sbase + ((unsigned)r << 9);
        asm volatile("cp.async.cg.shared.global [%0], [%1], 16;\n"
                     :: "r"(dst), "l"(gp + r * TT));
        asm volatile("cp.async.commit_group;\n");
    }

    float d0 = INF_F, d1 = INF_F, d2 = INF_F, d3 = INF_F;
    float dl = (lane == 0) ? 0.0f : INF_F;   // D[i-1][4l-1] diagonal carry
    float expv = INF_F;                      // my d3 after previous step
    int   i = -lane;                         // my current row

    for (int s = 0; s < TT + 31; ++s, ++i) {
        int r = s + MARGIN;
        if (r < TT) {
            unsigned dst = sbase + ((unsigned)(r & (RING - 1)) << 9);
            asm volatile("cp.async.cg.shared.global [%0], [%1], 16;\n"
                         :: "r"(dst), "l"(gp + r * TT));
        }
        asm volatile("cp.async.commit_group;\n");
        asm volatile("cp.async.wait_group %0;\n" :: "n"(MARGIN));
        // after wait: rows 0..s are resident; lane reads row i = s - lane <= s

        // neighbor's row-i last column D[i][4l-1] (produced at step s-1)
        float v = __shfl_up_sync(FULLM, expv, 1);
        if (lane == 0) v = INF_F;

        float4 c = *(const float4*)(ring + ((i & (RING - 1)) << 7) + (lane << 2));
        if (i < 0) { c.x = INF_F; c.y = INF_F; c.z = INF_F; c.w = INF_F; }

        float t0 = fminf(d0, dl);
        float m1 = fminf(d1, d0);
        float m2 = fminf(d2, d1);
        float m3 = fminf(d3, d2);
        float x0 = fminf(t0, v)  + c.x;
        float x1 = fminf(m1, x0) + c.y;
        float x2 = fminf(m2, x1) + c.z;
        float x3 = fminf(m3, x2) + c.w;

        d0 = x0; d1 = x1; d2 = x2; d3 = x3;
        expv = x3;
        dl = v;
    }
    if (lane == 31) g_dists[p] = d3;   // D[127][127], computed at s = 158
}

// ---------------------------------------------------------------------------
// Kernel 2: single-block exact radix top-K + weights + elite compaction.
// ---------------------------------------------------------------------------
__global__ void __launch_bounds__(1024) select_kernel() {
    __shared__ unsigned hist[256];
    __shared__ unsigned wsum[32];
    __shared__ float    fred[32];
    __shared__ int      ired[32];
    __shared__ int      pofs[32];
    __shared__ float    s_min, s_Se;
    __shared__ unsigned s_prefix;
    __shared__ int      s_krem, s_cnt_lt;

    int tid = threadIdx.x, lane = tid & 31, wid = tid >> 5;

    float d[4]; unsigned u[4];
    float lmin = INF_F;
    #pragma unroll
    for (int e = 0; e < 4; ++e) {
        float x = g_dists[tid * 4 + e];
        d[e] = x;
        unsigned b = __float_as_uint(x);
        u[e] = b ^ ((b & 0x80000000u) ? 0xFFFFFFFFu : 0x80000000u);
        lmin = fminf(lmin, x);
    }
    if (tid == 0) { s_prefix = 0; s_krem = KSEL; s_cnt_lt = 0; }

    #pragma unroll
    for (int o = 16; o; o >>= 1) lmin = fminf(lmin, __shfl_xor_sync(FULLM, lmin, o));
    if (lane == 0) fred[wid] = lmin;
    __syncthreads();
    if (wid == 0) {
        float v = fred[lane];
        #pragma unroll
        for (int o = 16; o; o >>= 1) v = fminf(v, __shfl_xor_sync(FULLM, v, o));
        if (lane == 0) s_min = v;
    }
    __syncthreads();

    for (int shift = 24; shift >= 0; shift -= 8) {
        if (tid < 256) hist[tid] = 0;
        __syncthreads();
        unsigned pref  = s_prefix;
        int      krem  = s_krem;
        unsigned hmask = (shift == 24) ? 0u : (0xFFFFFFFFu << (shift + 8));
        #pragma unroll
        for (int e = 0; e < 4; ++e)
            if ((u[e] & hmask) == pref) atomicAdd(&hist[(u[e] >> shift) & 255], 1u);
        __syncthreads();
        unsigned v = 0, inc = 0;
        if (tid < 256) {
            v = hist[tid];
            inc = v;
            #pragma unroll
            for (int o = 1; o < 32; o <<= 1) {
                unsigned x = __shfl_up_sync(FULLM, inc, o);
                if (lane >= o) inc += x;
            }
            if (lane == 31) wsum[wid] = inc;
        }
        __syncthreads();
        if (tid < 256) {
            unsigned off = 0;
            #pragma unroll
            for (int k = 0; k < 8; ++k) off += (k < wid) ? wsum[k] : 0u;
            unsigned cum  = off + inc;
            unsigned prev = cum - v;
            if (prev < (unsigned)krem && (unsigned)krem <= cum) {
                s_prefix = pref | ((unsigned)tid << shift);
                s_krem   = krem - (int)prev;
            }
        }
        __syncthreads();
    }
    unsigned tau = s_prefix;

    int clt = 0, tc = 0;
    #pragma unroll
    for (int e = 0; e < 4; ++e) { clt += (u[e] < tau); tc += (u[e] == tau); }
    atomicAdd(&s_cnt_lt, clt);

    int incl = tc;
    #pragma unroll
    for (int o = 1; o < 32; o <<= 1) { int v = __shfl_up_sync(FULLM, incl, o); if (lane >= o) incl += v; }
    if (lane == 31) ired[wid] = incl;
    __syncthreads();
    if (wid == 0) {
        int v = ired[lane], s = v;
        #pragma unroll
        for (int o = 1; o < 32; o <<= 1) { int w2 = __shfl_up_sync(FULLM, s, o); if (lane >= o) s += w2; }
        ired[lane] = s - v;
    }
    __syncthreads();

    int trank = ired[wid] + (incl - tc);
    int need  = KSEL - s_cnt_lt;
    float mind = s_min;

    bool  sel[4]; float ws[4]; float esum = 0.f; int nsel = 0;
    #pragma unroll
    for (int e = 0; e < 4; ++e) {
        bool s = (u[e] < tau);
        if (u[e] == tau) { s = (trank < need); trank++; }
        sel[e] = s;
        float w = s ? expf(TEMP_F * (mind - d[e])) : 0.f;
        ws[e] = w; esum += w; nsel += s;
    }

    float se = esum;
    #pragma unroll
    for (int o = 16; o; o >>= 1) se += __shfl_xor_sync(FULLM, se, o);
    if (lane == 0) fred[wid] = se;
    __syncthreads();
    if (wid == 0) {
        float v = fred[lane];
        #pragma unroll
        for (int o = 16; o; o >>= 1) v += __shfl_xor_sync(FULLM, v, o);
        if (lane == 0) s_Se = v;
    }
    __syncthreads();
    float Se = s_Se;

    int pincl = nsel;
    #pragma unroll
    for (int o = 1; o < 32; o <<= 1) { int v = __shfl_up_sync(FULLM, pincl, o); if (lane >= o) pincl += v; }
    if (lane == 31) pofs[wid] = pincl;
    __syncthreads();
    if (wid == 0) {
        int v = pofs[lane], s = v;
        #pragma unroll
        for (int o = 1; o < 32; o <<= 1) { int w2 = __shfl_up_sync(FULLM, s, o); if (lane >= o) s += w2; }
        pofs[lane] = s - v;
    }
    __syncthreads();
    int pos = pofs[wid] + (pincl - nsel);

    float ssl = 0.f;
    #pragma unroll
    for (int e = 0; e < 4; ++e) {
        if (sel[e]) {
            float sc = ws[e] / Se;
            g_eidx[pos] = tid * 4 + e;
            g_ew[pos]   = sc;
            pos++;
            ssl += sc;
        }
    }

    #pragma unroll
    for (int o = 16; o; o >>= 1) ssl += __shfl_xor_sync(FULLM, ssl, o);
    if (lane == 0) fred[wid] = ssl;
    __syncthreads();
    if (wid == 0) {
        float v = fred[lane];
        #pragma unroll
        for (int o = 16; o; o >>= 1) v += __shfl_xor_sync(FULLM, v, o);
        if (lane == 0) g_ssum = v;
    }
}

// ---------------------------------------------------------------------------
// Kernel 3: weighted mean/std over the compacted elite list. One block per t.
// ---------------------------------------------------------------------------
__global__ void __launch_bounds__(512) reduce_kernel(const float* __restrict__ means,
                                                     const float* __restrict__ stds,
                                                     const float* __restrict__ noise,
                                                     float* __restrict__ out) {
    __shared__ float s1s[16][AA];
    __shared__ float s2s[16][AA];
    int t  = blockIdx.x;
    int a  = threadIdx.x & 31;
    int wg = threadIdx.x >> 5;

    float mn = means[t * AA + a];
    float sd = stds[t * AA + a];
    const float* np = noise + (size_t)t * PP * AA;

    float s1 = 0.f, s2 = 0.f;
    #pragma unroll 4
    for (int k = wg; k < KSEL; k += 16) {
        int   p = g_eidx[k];
        float w = g_ew[k];
        float x = fmaf(sd, __ldg(&np[(size_t)p * AA + a]), mn);
        x = fminf(fmaxf(x, -1.f), 1.f);
        s1 = fmaf(w, x, s1);
        s2 = fmaf(w * x, x, s2);
    }
    s1s[wg][a] = s1; s2s[wg][a] = s2;
    __syncthreads();

    if (wg == 0) {
        float S1 = 0.f, S2 = 0.f;
        #pragma unroll
        for (int k = 0; k < 16; ++k) { S1 += s1s[k][a]; S2 += s2s[k][a]; }
        float ssum  = g_ssum;
        float denom = ssum + 1e-9f;
        float m   = S1 / denom;
        float var = (S2 - 2.f * m * S1 + m * m * ssum) / denom;
        var = fmaxf(var, 0.f);
        float st = sqrtf(var);
        st = fminf(fmaxf(st, 0.05f), 1.0f);
        out[t * AA + a]           = 0.1f * mn + 0.9f * m;
        out[TT * AA + t * AA + a] = st;
    }
}

extern "C" void kernel_launch(void* const* d_in, const int* in_sizes, int n_in,
                              void* d_out, int out_size) {
    const float* obs   = (const float*)d_in[0];  // [P, T, T]
    const float* means = (const float*)d_in[1];  // [T, 1, A]
    const float* stds  = (const float*)d_in[2];  // [T, 1, A]
    const float* noise = (const float*)d_in[3];  // [T, P, A]
    float* out = (float*)d_out;                  // [2, T, 1, A]

    dtw_kernel<<<PP, 32>>>(obs);                 // one 32-thread block per p
    select_kernel<<<1, 1024>>>();
    reduce_kernel<<<TT, 512>>>(means, stds, noise, out);
}

// round 15
// speedup vs baseline: 1.5413x; 1.1484x over previous
#include <cuda_runtime.h>
#include <cuda_bf16.h>

#define PP   4096
#define TT   128
#define AA   32
#define KSEL 409
#define INF_F 1e30f
#define TEMP_F 0.5f
#define FULLM 0xffffffffu
#define RINGR  44      // live span = 31 (read window) + 12 (MARGIN) + 1 = 44 rows, 22 KB
#define MARGIN 12      // cp.async rows in flight

__device__ float    g_dists[PP];
__device__ int      g_eidx[KSEL];
__device__ float    g_ew[KSEL];
__device__ float    g_ssum;

// ---------------------------------------------------------------------------
// Kernel 1: DTW min-plus DP, skewed anti-diagonal. One 32-thread block per p.
// Lane l owns cols 4l..4l+3; at step s it computes row i = s - l.
// 22 KB ring (exact live span, incremental wrap -> no modulo) gives 10
// blocks/SM vs 6 with the 32 KB pow2 ring: the R11 profile showed the kernel
// latency-starved (occ 8.6%, issue 34.7%, DRAM 58.9%) -> 1.67x concurrency.
// ---------------------------------------------------------------------------
__global__ void __launch_bounds__(32) dtw_kernel(const float* __restrict__ obs) {
    __shared__ float ring[RINGR * TT];   // 22528 B
    int lane = threadIdx.x;
    int p = blockIdx.x;

    const float* gp = obs + (size_t)p * (TT * TT) + lane * 4;
    unsigned sbase = (unsigned)__cvta_generic_to_shared(ring) + (lane << 4);

    // prologue: rows 0..MARGIN-1 in flight, one commit group per row
    #pragma unroll
    for (int r = 0; r < MARGIN; ++r) {
        unsigned dst = sbase + ((unsigned)r << 9);
        asm volatile("cp.async.cg.shared.global [%0], [%1], 16;\n"
                     :: "r"(dst), "l"(gp + r * TT));
        asm volatile("cp.async.commit_group;\n");
    }

    float d0 = INF_F, d1 = INF_F, d2 = INF_F, d3 = INF_F;
    float dl = (lane == 0) ? 0.0f : INF_F;   // D[i-1][4l-1] diagonal carry
    float expv = INF_F;                      // my d3 after previous step
    int   i = -lane;                         // my current row

    // incremental ring slots (equal i mod RINGR / r mod RINGR once valid)
    int rd = (RINGR - lane) % RINGR;         // slot of my row i (valid when i >= 0)
    int wr = MARGIN;                         // slot of row r = s + MARGIN

    for (int s = 0; s < TT + 31; ++s, ++i) {
        int r = s + MARGIN;
        if (r < TT) {
            unsigned dst = sbase + ((unsigned)wr << 9);
            asm volatile("cp.async.cg.shared.global [%0], [%1], 16;\n"
                         :: "r"(dst), "l"(gp + r * TT));
        }
        asm volatile("cp.async.commit_group;\n");
        asm volatile("cp.async.wait_group %0;\n" :: "n"(MARGIN));
        // after wait: rows 0..s resident; lane reads row i = s - lane <= s

        // neighbor's row-i last column D[i][4l-1] (produced at step s-1)
        float v = __shfl_up_sync(FULLM, expv, 1);
        if (lane == 0) v = INF_F;

        float4 c = *(const float4*)(ring + (rd << 7) + (lane << 2));
        if (i < 0) { c.x = INF_F; c.y = INF_F; c.z = INF_F; c.w = INF_F; }

        float t0 = fminf(d0, dl);
        float m1 = fminf(d1, d0);
        float m2 = fminf(d2, d1);
        float m3 = fminf(d3, d2);
        float x0 = fminf(t0, v)  + c.x;
        float x1 = fminf(m1, x0) + c.y;
        float x2 = fminf(m2, x1) + c.z;
        float x3 = fminf(m3, x2) + c.w;

        d0 = x0; d1 = x1; d2 = x2; d3 = x3;
        expv = x3;
        dl = v;

        rd = (rd + 1 == RINGR) ? 0 : rd + 1;
        wr = (wr + 1 == RINGR) ? 0 : wr + 1;
    }
    if (lane == 31) g_dists[p] = d3;   // D[127][127], computed at s = 158
}

// ---------------------------------------------------------------------------
// Kernel 2: single-block exact radix top-K + weights + elite compaction.
// ---------------------------------------------------------------------------
__global__ void __launch_bounds__(1024) select_kernel() {
    __shared__ unsigned hist[256];
    __shared__ unsigned wsum[32];
    __shared__ float    fred[32];
    __shared__ int      ired[32];
    __shared__ int      pofs[32];
    __shared__ float    s_min, s_Se;
    __shared__ unsigned s_prefix;
    __shared__ int      s_krem, s_cnt_lt;

    int tid = threadIdx.x, lane = tid & 31, wid = tid >> 5;

    float d[4]; unsigned u[4];
    float lmin = INF_F;
    #pragma unroll
    for (int e = 0; e < 4; ++e) {
        float x = g_dists[tid * 4 + e];
        d[e] = x;
        unsigned b = __float_as_uint(x);
        u[e] = b ^ ((b & 0x80000000u) ? 0xFFFFFFFFu : 0x80000000u);
        lmin = fminf(lmin, x);
    }
    if (tid == 0) { s_prefix = 0; s_krem = KSEL; s_cnt_lt = 0; }

    #pragma unroll
    for (int o = 16; o; o >>= 1) lmin = fminf(lmin, __shfl_xor_sync(FULLM, lmin, o));
    if (lane == 0) fred[wid] = lmin;
    __syncthreads();
    if (wid == 0) {
        float v = fred[lane];
        #pragma unroll
        for (int o = 16; o; o >>= 1) v = fminf(v, __shfl_xor_sync(FULLM, v, o));
        if (lane == 0) s_min = v;
    }
    __syncthreads();

    for (int shift = 24; shift >= 0; shift -= 8) {
        if (tid < 256) hist[tid] = 0;
        __syncthreads();
        unsigned pref  = s_prefix;
        int      krem  = s_krem;
        unsigned hmask = (shift == 24) ? 0u : (0xFFFFFFFFu << (shift + 8));
        #pragma unroll
        for (int e = 0; e < 4; ++e)
            if ((u[e] & hmask) == pref) atomicAdd(&hist[(u[e] >> shift) & 255], 1u);
        __syncthreads();
        unsigned v = 0, inc = 0;
        if (tid < 256) {
            v = hist[tid];
            inc = v;
            #pragma unroll
            for (int o = 1; o < 32; o <<= 1) {
                unsigned x = __shfl_up_sync(FULLM, inc, o);
                if (lane >= o) inc += x;
            }
            if (lane == 31) wsum[wid] = inc;
        }
        __syncthreads();
        if (tid < 256) {
            unsigned off = 0;
            #pragma unroll
            for (int k = 0; k < 8; ++k) off += (k < wid) ? wsum[k] : 0u;
            unsigned cum  = off + inc;
            unsigned prev = cum - v;
            if (prev < (unsigned)krem && (unsigned)krem <= cum) {
                s_prefix = pref | ((unsigned)tid << shift);
                s_krem   = krem - (int)prev;
            }
        }
        __syncthreads();
    }
    unsigned tau = s_prefix;

    int clt = 0, tc = 0;
    #pragma unroll
    for (int e = 0; e < 4; ++e) { clt += (u[e] < tau); tc += (u[e] == tau); }
    atomicAdd(&s_cnt_lt, clt);

    int incl = tc;
    #pragma unroll
    for (int o = 1; o < 32; o <<= 1) { int v = __shfl_up_sync(FULLM, incl, o); if (lane >= o) incl += v; }
    if (lane == 31) ired[wid] = incl;
    __syncthreads();
    if (wid == 0) {
        int v = ired[lane], s = v;
        #pragma unroll
        for (int o = 1; o < 32; o <<= 1) { int w2 = __shfl_up_sync(FULLM, s, o); if (lane >= o) s += w2; }
        ired[lane] = s - v;
    }
    __syncthreads();

    int trank = ired[wid] + (incl - tc);
    int need  = KSEL - s_cnt_lt;
    float mind = s_min;

    bool  sel[4]; float ws[4]; float esum = 0.f; int nsel = 0;
    #pragma unroll
    for (int e = 0; e < 4; ++e) {
        bool s = (u[e] < tau);
        if (u[e] == tau) { s = (trank < need); trank++; }
        sel[e] = s;
        float w = s ? expf(TEMP_F * (mind - d[e])) : 0.f;
        ws[e] = w; esum += w; nsel += s;
    }

    float se = esum;
    #pragma unroll
    for (int o = 16; o; o >>= 1) se += __shfl_xor_sync(FULLM, se, o);
    if (lane == 0) fred[wid] = se;
    __syncthreads();
    if (wid == 0) {
        float v = fred[lane];
        #pragma unroll
        for (int o = 16; o; o >>= 1) v += __shfl_xor_sync(FULLM, v, o);
        if (lane == 0) s_Se = v;
    }
    __syncthreads();
    float Se = s_Se;

    int pincl = nsel;
    #pragma unroll
    for (int o = 1; o < 32; o <<= 1) { int v = __shfl_up_sync(FULLM, pincl, o); if (lane >= o) pincl += v; }
    if (lane == 31) pofs[wid] = pincl;
    __syncthreads();
    if (wid == 0) {
        int v = pofs[lane], s = v;
        #pragma unroll
        for (int o = 1; o < 32; o <<= 1) { int w2 = __shfl_up_sync(FULLM, s, o); if (lane >= o) s += w2; }
        pofs[lane] = s - v;
    }
    __syncthreads();
    int pos = pofs[wid] + (pincl - nsel);

    float ssl = 0.f;
    #pragma unroll
    for (int e = 0; e < 4; ++e) {
        if (sel[e]) {
            float sc = ws[e] / Se;
            g_eidx[pos] = tid * 4 + e;
            g_ew[pos]   = sc;
            pos++;
            ssl += sc;
        }
    }

    #pragma unroll
    for (int o = 16; o; o >>= 1) ssl += __shfl_xor_sync(FULLM, ssl, o);
    if (lane == 0) fred[wid] = ssl;
    __syncthreads();
    if (wid == 0) {
        float v = fred[lane];
        #pragma unroll
        for (int o = 16; o; o >>= 1) v += __shfl_xor_sync(FULLM, v, o);
        if (lane == 0) g_ssum = v;
    }
}

// ---------------------------------------------------------------------------
// Kernel 3: weighted mean/std over the compacted elite list. One block per t.
// ---------------------------------------------------------------------------
__global__ void __launch_bounds__(512) reduce_kernel(const float* __restrict__ means,
                                                     const float* __restrict__ stds,
                                                     const float* __restrict__ noise,
                                                     float* __restrict__ out) {
    __shared__ float s1s[16][AA];
    __shared__ float s2s[16][AA];
    int t  = blockIdx.x;
    int a  = threadIdx.x & 31;
    int wg = threadIdx.x >> 5;

    float mn = means[t * AA + a];
    float sd = stds[t * AA + a];
    const float* np = noise + (size_t)t * PP * AA;

    float s1 = 0.f, s2 = 0.f;
    #pragma unroll 4
    for (int k = wg; k < KSEL; k += 16) {
        int   p = g_eidx[k];
        float w = g_ew[k];
        float x = fmaf(sd, __ldg(&np[(size_t)p * AA + a]), mn);
        x = fminf(fmaxf(x, -1.f), 1.f);
        s1 = fmaf(w, x, s1);
        s2 = fmaf(w * x, x, s2);
    }
    s1s[wg][a] = s1; s2s[wg][a] = s2;
    __syncthreads();

    if (wg == 0) {
        float S1 = 0.f, S2 = 0.f;
        #pragma unroll
        for (int k = 0; k < 16; ++k) { S1 += s1s[k][a]; S2 += s2s[k][a]; }
        float ssum  = g_ssum;
        float denom = ssum + 1e-9f;
        float m   = S1 / denom;
        float var = (S2 - 2.f * m * S1 + m * m * ssum) / denom;
        var = fmaxf(var, 0.f);
        float st = sqrtf(var);
        st = fminf(fmaxf(st, 0.05f), 1.0f);
        out[t * AA + a]           = 0.1f * mn + 0.9f * m;
        out[TT * AA + t * AA + a] = st;
    }
}

extern "C" void kernel_launch(void* const* d_in, const int* in_sizes, int n_in,
                              void* d_out, int out_size) {
    const float* obs   = (const float*)d_in[0];  // [P, T, T]
    const float* means = (const float*)d_in[1];  // [T, 1, A]
    const float* stds  = (const float*)d_in[2];  // [T, 1, A]
    const float* noise = (const float*)d_in[3];  // [T, P, A]
    float* out = (float*)d_out;                  // [2, T, 1, A]

    dtw_kernel<<<PP, 32>>>(obs);                 // one 32-thread block per p
    select_kernel<<<1, 1024>>>();
    reduce_kernel<<<TT, 512>>>(means, stds, noise, out);
}